// round 11
// baseline (speedup 1.0000x reference)
#include <cuda_runtime.h>

// Problem constants
#define LL 8
#define KK 8
#define NN 1048576
#define NVEC (NN / 4)          // 262144 float4 per (l,k) row
#define NPAIR 36               // triangular 8x8
#define NSM 148
#define OCC 2
#define NCTA (NSM * OCC)       // 296 CTAs, all resident (2/SM guaranteed)
#define THREADS 256
#define PAD 32                 // pad tri entries to separate 128B lines

// Scratch (allocation-free rule: __device__ globals)
__device__ float    g_tri[LL][NPAIR * PAD];   // padded triangular Gram sums
__device__ unsigned g_bar[LL];                 // per-layer barrier counters

__device__ __forceinline__ int tri_idx(int a, int b) {
    return a * KK - (a * (a - 1)) / 2 + (b - a);
}

// ---------------------------------------------------------------------------
// Init: reset barrier counters + zero tri accumulators (every replay)
// ---------------------------------------------------------------------------
__global__ void init_kernel() {
    const int t = threadIdx.x;
    if (t < LL) g_bar[t] = 0u;
    float* p = reinterpret_cast<float*>(g_tri);
    for (int i = t; i < LL * NPAIR * PAD; i += blockDim.x) p[i] = 0.0f;
}

// ---------------------------------------------------------------------------
// Persistent fused kernel, SEQUENTIAL per-layer schedule (R7's L2-reuse-safe
// order) + last(l) L2 prefetch issued before the barrier wait, so the wait
// and gram's DRAM headroom fetch data apply(l) needs anyway. No deltas
// lookahead (R10 showed it evicts deltas(l) and costs ~214MB of re-reads).
// ---------------------------------------------------------------------------
__global__ void __launch_bounds__(THREADS, OCC)
fused_kernel(const float* __restrict__ last,
             const float* __restrict__ deltas,
             const float* __restrict__ beta,
             float* __restrict__ out) {
    const int tid  = threadIdx.x;
    const int cta  = blockIdx.x;
    const int lane = tid & 31;
    const int wid  = tid >> 5;

    __shared__ float sred[8][NPAIR];
    __shared__ float Ws[KK * KK];

    for (int l = 0; l < LL; ++l) {
        const float4* __restrict__ d4 =
            reinterpret_cast<const float4*>(deltas) + (size_t)l * KK * NVEC;
        const float4* __restrict__ p4 =
            reinterpret_cast<const float4*>(last) + (size_t)l * KK * NVEC;
        float4* __restrict__ o4 =
            reinterpret_cast<float4*>(out) + (size_t)l * KK * NVEC;

        // ---------------- Phase 1: Gram (double-chunk, 16 loads in flight) --
        float acc[NPAIR];
#pragma unroll
        for (int p = 0; p < NPAIR; ++p) acc[p] = 0.0f;

        const int stride = NCTA * THREADS;
        for (int i = cta * THREADS + tid; i < NVEC; i += 2 * stride) {
            const int i2 = i + stride;
            float4 v0[KK], v1[KK];
#pragma unroll
            for (int j = 0; j < KK; ++j) v0[j] = d4[(size_t)j * NVEC + i];
            const bool has2 = (i2 < NVEC);
#pragma unroll
            for (int j = 0; j < KK; ++j)
                v1[j] = has2 ? d4[(size_t)j * NVEC + i2]
                             : make_float4(0.f, 0.f, 0.f, 0.f);
            int p = 0;
#pragma unroll
            for (int a = 0; a < KK; ++a) {
#pragma unroll
                for (int b = a; b < KK; ++b) {
                    float s = fmaf(v0[a].x, v0[b].x, acc[p]);
                    s = fmaf(v0[a].y, v0[b].y, s);
                    s = fmaf(v0[a].z, v0[b].z, s);
                    s = fmaf(v0[a].w, v0[b].w, s);
                    s = fmaf(v1[a].x, v1[b].x, s);
                    s = fmaf(v1[a].y, v1[b].y, s);
                    s = fmaf(v1[a].z, v1[b].z, s);
                    s = fmaf(v1[a].w, v1[b].w, s);
                    acc[p] = s;
                    ++p;
                }
            }
        }

        // ------- Prefetch last(l) into L2 (async, fills wait dead-time) -----
        {
            const char* lp = reinterpret_cast<const char*>(p4);
            const size_t total = (size_t)KK * NVEC * sizeof(float4);  // 32 MB
            const size_t step  = (size_t)NCTA * THREADS * 128;
            for (size_t off = (size_t)(cta * THREADS + tid) * 128;
                 off < total; off += step)
                asm volatile("prefetch.global.L2 [%0];" :: "l"(lp + off));
        }

        // ---------------- cross-warp reduce + arrive ------------------------
        __syncthreads();   // sred reuse guard
#pragma unroll
        for (int p = 0; p < NPAIR; ++p) {
            float v = acc[p];
#pragma unroll
            for (int o = 16; o > 0; o >>= 1)
                v += __shfl_down_sync(0xffffffffu, v, o);
            if (lane == 0) sred[wid][p] = v;
        }
        __syncthreads();
        if (tid < NPAIR) {
            float s = 0.0f;
#pragma unroll
            for (int w = 0; w < 8; ++w) s += sred[w][tid];
            atomicAdd(&g_tri[l][tid * PAD], s);
        }
        __threadfence();
        __syncthreads();
        if (tid == 0) {
            atomicAdd(&g_bar[l], 1u);
            while (*(volatile unsigned*)&g_bar[l] < NCTA) __nanosleep(32);
        }
        __syncthreads();
        __threadfence();

        // ---------------- Phase 2: softmax -> Ws in smem --------------------
        if (tid < KK) {
            const int k = tid;
            const float scale = rsqrtf((float)NN);
            float v[KK];
            float m = -1e30f;
#pragma unroll
            for (int j = 0; j < KK; ++j) {
                int a = k < j ? k : j;
                int b = k < j ? j : k;
                v[j] = g_tri[l][tri_idx(a, b) * PAD] * scale;
                m = fmaxf(m, v[j]);
            }
            float s = 0.0f;
#pragma unroll
            for (int j = 0; j < KK; ++j) {
                v[j] = __expf(v[j] - m);
                s += v[j];
            }
            float inv = 1.0f / s;
            float bcl = fminf(fmaxf(beta[l * KK + k], 0.0f), 1.0f);
#pragma unroll
            for (int j = 0; j < KK; ++j)
                Ws[k * KK + j] = bcl * v[j] * inv + ((j == k) ? 1.0f : 0.0f);
        }
        __syncthreads();

        // ---------------- Phase 3: apply (deltas + last hit L2) -------------
        for (int i = cta * THREADS + tid; i < NVEC; i += stride) {
            float4 oacc[KK];
#pragma unroll
            for (int k = 0; k < KK; ++k)
                oacc[k] = p4[(size_t)k * NVEC + i];            // L2 (prefetched)
#pragma unroll
            for (int j = 0; j < KK; ++j) {
                float4 v = d4[(size_t)j * NVEC + i];           // L2 (gram-resident)
#pragma unroll
                for (int k = 0; k < KK; ++k) {
                    float w = Ws[k * KK + j];
                    oacc[k].x = fmaf(w, v.x, oacc[k].x);
                    oacc[k].y = fmaf(w, v.y, oacc[k].y);
                    oacc[k].z = fmaf(w, v.z, oacc[k].z);
                    oacc[k].w = fmaf(w, v.w, oacc[k].w);
                }
            }
#pragma unroll
            for (int k = 0; k < KK; ++k)
                __stcs(&o4[(size_t)k * NVEC + i], oacc[k]);    // evict-first
        }
        __syncthreads();   // Ws/sred safe for next layer's reuse
    }
}

// ---------------------------------------------------------------------------
extern "C" void kernel_launch(void* const* d_in, const int* in_sizes, int n_in,
                              void* d_out, int out_size) {
    const float* last_params = (const float*)d_in[0];
    const float* deltas      = (const float*)d_in[1];
    const float* beta        = (const float*)d_in[2];
    float* out               = (float*)d_out;

    init_kernel<<<1, 1024>>>();
    fused_kernel<<<NCTA, THREADS>>>(last_params, deltas, beta, out);
}

// round 12
// speedup vs baseline: 1.0935x; 1.0935x over previous
#include <cuda_runtime.h>

// Problem constants
#define LL 8
#define KK 8
#define NN 1048576
#define NVEC (NN / 4)          // 262144 float4 per (l,k) row
#define NPAIR 36               // triangular 8x8
#define NSM 148
#define OCC 2
#define NCTA (NSM * OCC)       // 296 CTAs, all resident (2/SM guaranteed)
#define THREADS 256
#define PAD 32                 // pad tri entries to separate 128B lines

// Scratch (allocation-free rule: __device__ globals)
__device__ float    g_tri[LL][NPAIR * PAD];   // padded triangular Gram sums
__device__ unsigned g_bar[LL];                 // per-layer barrier counters

__device__ __forceinline__ int tri_idx(int a, int b) {
    return a * KK - (a * (a - 1)) / 2 + (b - a);
}

// L2 evict_last policy: lines loaded with this hint are sticky in L2.
__device__ __forceinline__ unsigned long long mk_sticky_policy() {
    unsigned long long p;
    asm("createpolicy.fractional.L2::evict_last.b64 %0, 1.0;" : "=l"(p));
    return p;
}
__device__ __forceinline__ float4 ld_sticky(const float4* a,
                                            unsigned long long pol) {
    float4 v;
    asm volatile("ld.global.L2::cache_hint.v4.f32 {%0,%1,%2,%3}, [%4], %5;"
                 : "=f"(v.x), "=f"(v.y), "=f"(v.z), "=f"(v.w)
                 : "l"(a), "l"(pol));
    return v;
}

// ---------------------------------------------------------------------------
// Init: reset barrier counters + zero tri accumulators (every replay)
// ---------------------------------------------------------------------------
__global__ void init_kernel() {
    const int t = threadIdx.x;
    if (t < LL) g_bar[t] = 0u;
    float* p = reinterpret_cast<float*>(g_tri);
    for (int i = t; i < LL * NPAIR * PAD; i += blockDim.x) p[i] = 0.0f;
}

// ---------------------------------------------------------------------------
// Persistent fused kernel, barrier-hiding schedule (R10) + L2 policy control:
//   gram(0); arrive(0)
//   for l: { gram(l+1) [evict_last]; arrive(l+1); wait(l); softmax(l);
//            apply(l) [deltas evict-first on last read] }
// gram's sticky loads pin deltas(l+1) in L2 through the overlap window;
// apply demotes deltas(l) as it consumes it. Streams (last/out) evict-first.
// ---------------------------------------------------------------------------
__global__ void __launch_bounds__(THREADS, OCC)
fused_kernel(const float* __restrict__ last,
             const float* __restrict__ deltas,
             const float* __restrict__ beta,
             float* __restrict__ out) {
    const int tid  = threadIdx.x;
    const int cta  = blockIdx.x;
    const int lane = tid & 31;
    const int wid  = tid >> 5;
    const unsigned long long pol = mk_sticky_policy();

    __shared__ float sred[8][NPAIR];
    __shared__ float Ws[KK * KK];

    // ------------------- gram phase for one layer -------------------------
    auto do_gram = [&](int l) {
        const float4* __restrict__ d4 =
            reinterpret_cast<const float4*>(deltas) + (size_t)l * KK * NVEC;

        float acc[NPAIR];
#pragma unroll
        for (int p = 0; p < NPAIR; ++p) acc[p] = 0.0f;

        const int stride = NCTA * THREADS;
        for (int i = cta * THREADS + tid; i < NVEC; i += 2 * stride) {
            const int i2 = i + stride;
            float4 v0[KK], v1[KK];
#pragma unroll
            for (int j = 0; j < KK; ++j)
                v0[j] = ld_sticky(&d4[(size_t)j * NVEC + i], pol);
            const bool has2 = (i2 < NVEC);
#pragma unroll
            for (int j = 0; j < KK; ++j)
                v1[j] = has2 ? ld_sticky(&d4[(size_t)j * NVEC + i2], pol)
                             : make_float4(0.f, 0.f, 0.f, 0.f);
            int p = 0;
#pragma unroll
            for (int a = 0; a < KK; ++a) {
#pragma unroll
                for (int b = a; b < KK; ++b) {
                    float s = fmaf(v0[a].x, v0[b].x, acc[p]);
                    s = fmaf(v0[a].y, v0[b].y, s);
                    s = fmaf(v0[a].z, v0[b].z, s);
                    s = fmaf(v0[a].w, v0[b].w, s);
                    s = fmaf(v1[a].x, v1[b].x, s);
                    s = fmaf(v1[a].y, v1[b].y, s);
                    s = fmaf(v1[a].z, v1[b].z, s);
                    s = fmaf(v1[a].w, v1[b].w, s);
                    acc[p] = s;
                    ++p;
                }
            }
        }

        // cross-warp reduce (sred reuse guarded by this syncthreads)
        __syncthreads();
#pragma unroll
        for (int p = 0; p < NPAIR; ++p) {
            float v = acc[p];
#pragma unroll
            for (int o = 16; o > 0; o >>= 1)
                v += __shfl_down_sync(0xffffffffu, v, o);
            if (lane == 0) sred[wid][p] = v;
        }
        __syncthreads();
        if (tid < NPAIR) {
            float s = 0.0f;
#pragma unroll
            for (int w = 0; w < 8; ++w) s += sred[w][tid];
            atomicAdd(&g_tri[l][tid * PAD], s);
        }
        // arrive: release our g_tri contribution, bump layer counter
        __threadfence();
        __syncthreads();
        if (tid == 0) atomicAdd(&g_bar[l], 1u);
    };

    // ------------------------------- schedule -----------------------------
    do_gram(0);

    for (int l = 0; l < LL; ++l) {
        if (l + 1 < LL) do_gram(l + 1);   // hides the wait below

        // wait for all gram(l) contributions
        if (tid == 0) {
            while (*(volatile unsigned*)&g_bar[l] < NCTA) __nanosleep(32);
        }
        __syncthreads();
        __threadfence();

        // softmax -> Ws in smem (every CTA redundantly; 8 threads)
        if (tid < KK) {
            const int k = tid;
            const float scale = rsqrtf((float)NN);
            float v[KK];
            float m = -1e30f;
#pragma unroll
            for (int j = 0; j < KK; ++j) {
                int a = k < j ? k : j;
                int b = k < j ? j : k;
                v[j] = g_tri[l][tri_idx(a, b) * PAD] * scale;
                m = fmaxf(m, v[j]);
            }
            float s = 0.0f;
#pragma unroll
            for (int j = 0; j < KK; ++j) {
                v[j] = __expf(v[j] - m);
                s += v[j];
            }
            float inv = 1.0f / s;
            float bcl = fminf(fmaxf(beta[l * KK + k], 0.0f), 1.0f);
#pragma unroll
            for (int j = 0; j < KK; ++j)
                Ws[k * KK + j] = bcl * v[j] * inv + ((j == k) ? 1.0f : 0.0f);
        }
        __syncthreads();

        // apply: out = last + Ws * deltas.  Last reader of deltas(l):
        // __ldcs demotes each consumed line, freeing sticky capacity.
        const float4* __restrict__ d4 =
            reinterpret_cast<const float4*>(deltas) + (size_t)l * KK * NVEC;
        const float4* __restrict__ p4 =
            reinterpret_cast<const float4*>(last) + (size_t)l * KK * NVEC;
        float4* __restrict__ o4 =
            reinterpret_cast<float4*>(out) + (size_t)l * KK * NVEC;

        for (int i = cta * THREADS + tid; i < NVEC; i += NCTA * THREADS) {
            float4 oacc[KK];
#pragma unroll
            for (int k = 0; k < KK; ++k)
                oacc[k] = __ldcs(&p4[(size_t)k * NVEC + i]);   // stream
#pragma unroll
            for (int j = 0; j < KK; ++j) {
                float4 v = __ldcs(&d4[(size_t)j * NVEC + i]);  // L2 hit + demote
#pragma unroll
                for (int k = 0; k < KK; ++k) {
                    float w = Ws[k * KK + j];
                    oacc[k].x = fmaf(w, v.x, oacc[k].x);
                    oacc[k].y = fmaf(w, v.y, oacc[k].y);
                    oacc[k].z = fmaf(w, v.z, oacc[k].z);
                    oacc[k].w = fmaf(w, v.w, oacc[k].w);
                }
            }
#pragma unroll
            for (int k = 0; k < KK; ++k)
                __stcs(&o4[(size_t)k * NVEC + i], oacc[k]);    // stream
        }
        __syncthreads();   // Ws/sred safe for next layer's reuse
    }
}

// ---------------------------------------------------------------------------
extern "C" void kernel_launch(void* const* d_in, const int* in_sizes, int n_in,
                              void* d_out, int out_size) {
    const float* last_params = (const float*)d_in[0];
    const float* deltas      = (const float*)d_in[1];
    const float* beta        = (const float*)d_in[2];
    float* out               = (float*)d_out;

    init_kernel<<<1, 1024>>>();
    fused_kernel<<<NCTA, THREADS>>>(last_params, deltas, beta, out);
}